// round 13
// baseline (speedup 1.0000x reference)
#include <cuda_runtime.h>

#define BB   32
#define LL   2048
#define DIN  64
#define NC   32
#define DC   16
#define NOUT 512        // NC*DC
#define NCH  16         // chunks for heavy iter kernel
#define LCH  (LL/NCH)   // 128 rows per CTA
#define TILES 4         // 32-row tiles
#define NCH0 32         // chunks for iteration-0 reduction
#define ROWS0 (LL/NCH0) // 64 rows per CTA

// Scratch (no allocations allowed) ------------------------------------------
__device__ float g_part0[BB * NCH0 * DIN];      // iter-0 partial sums (256 KB)
__device__ float g_part [BB * NCH  * NC * DIN]; // per-chunk s partials (4 MB)
__device__ float g_v    [BB * NC * DIN];        // v[b,n,i] = W_n . outputs[b,n,:]

// Packed f32x2 helpers -------------------------------------------------------
__device__ __forceinline__ void ffma2(unsigned long long& d,
                                      unsigned long long a,
                                      unsigned long long b) {
    asm volatile("fma.rn.f32x2 %0, %1, %2, %0;" : "+l"(d) : "l"(a), "l"(b));
}
__device__ __forceinline__ void addf2(unsigned long long& d, unsigned long long a) {
    asm volatile("add.rn.f32x2 %0, %0, %1;" : "+l"(d) : "l"(a));
}
__device__ __forceinline__ void lds_v2b64(unsigned long long& a,
                                          unsigned long long& b,
                                          unsigned addr) {
    asm volatile("ld.shared.v2.b64 {%0, %1}, [%2];" : "=l"(a), "=l"(b) : "r"(addr));
}
__device__ __forceinline__ unsigned long long pack2(float x, float y) {
    unsigned long long r;
    asm("mov.b64 %0, {%1, %2};" : "=l"(r) : "f"(x), "f"(y));
    return r;
}
__device__ __forceinline__ float2 unpack2(unsigned long long v) {
    float2 r;
    asm("mov.b64 {%0, %1}, %2;" : "=f"(r.x), "=f"(r.y) : "l"(v));
    return r;
}
__device__ __forceinline__ void bar_pair(int id) {
    asm volatile("bar.sync %0, 64;" :: "r"(id));
}
__device__ __forceinline__ void cp_async16(unsigned saddr, const void* gaddr) {
    asm volatile("cp.async.ca.shared.global [%0], [%1], 16;"
                 :: "r"(saddr), "l"(gaddr));
}
__device__ __forceinline__ void cp_commit() {
    asm volatile("cp.async.commit_group;");
}
template <int N>
__device__ __forceinline__ void cp_wait() {
    asm volatile("cp.async.wait_group %0;" :: "n"(N));
}

// ----------------------------------------------------------------------------
// Dummy kernel: shifts the second iter_kernel to global launch index 5 so the
// harness's fixed "ncu -s 5 -c 1" capture profiles iter instead of finalize.
// ----------------------------------------------------------------------------
__global__ void dummy_kernel() {}

// ----------------------------------------------------------------------------
// Kernel 1: iteration-0 reduction. c = softmax(0) is uniform, so
// s is (up to scale; squash is scale-invariant) just sum_l u[b,l,i].
// grid (NCH0, B), block 256.
// ----------------------------------------------------------------------------
__global__ __launch_bounds__(256) void reduce0_kernel(const float* __restrict__ u) {
    int b = blockIdx.y, ch = blockIdx.x;
    int t = threadIdx.x;
    int g = t >> 6, i = t & 63;
    const float* up = u + ((size_t)b * LL + (size_t)ch * ROWS0 + g) * DIN + i;
    float acc = 0.f;
#pragma unroll
    for (int j = 0; j < ROWS0 / 4; j++) acc += up[(size_t)j * 4 * DIN];
    __shared__ float red[4][64];
    red[g][i] = acc;
    __syncthreads();
    if (t < 64) {
        float s = red[0][t] + red[1][t] + red[2][t] + red[3][t];
        g_part0[((size_t)b * NCH0 + ch) * DIN + t] = s;
    }
}

// ----------------------------------------------------------------------------
// Kernel 2: finalize, one CTA (4 warps) per (b, n) capsule.
// grid (NC, B), block 128. Warp w reduces its share of chunks, smem combine,
// then warp 0 projects through W_n, squashes, writes out / v.
// ----------------------------------------------------------------------------
__global__ __launch_bounds__(128) void finalize_kernel(int per_n,
                                                       const float* __restrict__ W,
                                                       float* __restrict__ out,
                                                       int want_v) {
    int b = blockIdx.y, n = blockIdx.x;
    int w = threadIdx.x >> 5, lane = threadIdx.x & 31;

    // 1. parallel chunk reduction across 4 warps
    float s0 = 0.f, s1 = 0.f;
    if (per_n) {
        const float* gp = g_part + (((size_t)b * NCH) * NC + n) * DIN;
#pragma unroll
        for (int ch = 0; ch < NCH / 4; ch++) {
            size_t off = (size_t)(w * (NCH / 4) + ch) * (NC * DIN);
            s0 += gp[off + lane];
            s1 += gp[off + lane + 32];
        }
    } else {
        const float* gp = g_part0 + (size_t)b * NCH0 * DIN;
#pragma unroll
        for (int ch = 0; ch < NCH0 / 4; ch++) {
            int off = (w * (NCH0 / 4) + ch) * DIN;
            s0 += gp[off + lane];
            s1 += gp[off + lane + 32];
        }
    }

    __shared__ float part[4][DIN];
    part[w][lane] = s0;
    part[w][lane + 32] = s1;
    __syncthreads();

    if (w != 0) return;

    __shared__ float s_sh[DIN];
    s_sh[lane]      = part[0][lane] + part[1][lane] + part[2][lane] + part[3][lane];
    s_sh[lane + 32] = part[0][lane + 32] + part[1][lane + 32] +
                      part[2][lane + 32] + part[3][lane + 32];
    __syncwarp();

    // 2. projection: o[d] = sum_i s[i] * W[i*512 + n*16 + d]
    int d = lane & 15, half = lane >> 4;
    float acc = 0.f;
    {
        const float* Wp = W + (size_t)(half * 32) * NOUT + n * DC + d;
#pragma unroll
        for (int i = 0; i < 32; i++)
            acc += s_sh[half * 32 + i] * Wp[(size_t)i * NOUT];
    }
    acc += __shfl_xor_sync(0xffffffffu, acc, 16);

    // 3. squash (pure L2 normalize, eps=1e-7), reduce within 16-lane group
    float s2 = acc * acc;
#pragma unroll
    for (int off = 8; off; off >>= 1)
        s2 += __shfl_xor_sync(0xffffffffu, s2, off, 16);
    float o = acc * rsqrtf(s2 + 1e-7f);

    if (out && lane < 16) out[(size_t)b * NOUT + n * DC + lane] = o;

    // 4. v[i] = sum_d o[d] * W[i*512 + n*16 + d]
    if (want_v) {
        const float4* w0 = (const float4*)(W + (size_t)lane * NOUT + n * DC);
        const float4* w1 = (const float4*)(W + (size_t)(lane + 32) * NOUT + n * DC);
        float v0 = 0.f, v1 = 0.f;
#pragma unroll
        for (int q = 0; q < 4; q++) {
            float4 a = w0[(size_t)q];
            float4 c = w1[(size_t)q];
            float o0 = __shfl_sync(0xffffffffu, o, 4 * q + 0);
            float o1 = __shfl_sync(0xffffffffu, o, 4 * q + 1);
            float o2 = __shfl_sync(0xffffffffu, o, 4 * q + 2);
            float o3 = __shfl_sync(0xffffffffu, o, 4 * q + 3);
            v0 += a.x * o0 + a.y * o1 + a.z * o2 + a.w * o3;
            v1 += c.x * o0 + c.y * o1 + c.z * o2 + c.w * o3;
        }
        float* vp = g_v + ((size_t)b * NC + n) * DIN;
        vp[lane] = v0;
        vp[lane + 32] = v1;
    }
}

// ----------------------------------------------------------------------------
// Kernel 3: fused routing iteration, i-split across warp pairs.
// Batched shared loads (MLP=8) before the FFMA2 chains; 4-row interleaved
// SHFL-butterfly softmax; cp.async double-buffered tiles; pair-scoped
// named barriers for the half-logit exchange.
// grid (NCH, B), block 128 (4 warps = 2 pairs; pair handles 16 rows/tile).
// ----------------------------------------------------------------------------
__global__ __launch_bounds__(128, 4) void iter_kernel(const float* __restrict__ u) {
    int b = blockIdx.y, ch = blockIdx.x;
    int t = threadIdx.x, w = t >> 5, lane = t & 31;
    int p = w >> 1, h = w & 1;

    __shared__ __align__(16) float4 ush4[2][32 * 16];       // 2 x 8 KB tiles
    __shared__ __align__(16) float  lg_sh[2][2][2][4][32];  // logits exch (4 KB)
    __shared__ __align__(16) float  red[32 * 66];           // s combine (8.25 KB)

    unsigned long long vreg[16], sreg[16];
    const unsigned long long* vp =
        (const unsigned long long*)(g_v + ((size_t)b * NC + lane) * DIN + h * 32);
#pragma unroll
    for (int k = 0; k < 16; k++) vreg[k] = vp[k];
#pragma unroll
    for (int k = 0; k < 16; k++) sreg[k] = 0ULL;

    unsigned ush_base = (unsigned)__cvta_generic_to_shared(&ush4[0][0]);
    const float4* ug = (const float4*)(u + ((size_t)b * LL + (size_t)ch * LCH) * DIN);

    // prologue: async-load tile 0 into buffer 0
#pragma unroll
    for (int j = 0; j < 4; j++)
        cp_async16(ush_base + (unsigned)((t + 128 * j) * 16), ug + t + 128 * j);
    cp_commit();

    for (int tile = 0; tile < TILES; tile++) {
        cp_wait<0>();        // tile's data resident
        __syncthreads();     // all warps done with the buffer we're about to fill

        if (tile + 1 < TILES) {
            unsigned dst = ush_base + (unsigned)(((tile + 1) & 1) * 8192);
            const float4* src = ug + (tile + 1) * 512;
#pragma unroll
            for (int j = 0; j < 4; j++)
                cp_async16(dst + (unsigned)((t + 128 * j) * 16), src + t + 128 * j);
            cp_commit();
        }

        unsigned ush_addr = ush_base + (unsigned)((tile & 1) * 8192);

        for (int rb = 0; rb < 4; rb++) {     // 4 batches of 4 rows per pair
            int buf = rb & 1;
            float hlg[4];
            // --- phase 1: half-logits for 4 rows (my 32 dims) ---
#pragma unroll
            for (int rr = 0; rr < 4; rr++) {
                unsigned addr = ush_addr +
                    (unsigned)((p * 16 + rb * 4 + rr) * 256 + h * 128);
                unsigned long long ua[8], ub[8];
#pragma unroll
                for (int k = 0; k < 8; k++)          // batch loads: MLP=8
                    lds_v2b64(ua[k], ub[k], addr + k * 16);
                unsigned long long a0 = 0ULL, a1 = 0ULL;
#pragma unroll
                for (int k = 0; k < 8; k++) {        // then the math
                    ffma2(a0, ua[k], vreg[2 * k + 0]);
                    ffma2(a1, ub[k], vreg[2 * k + 1]);
                }
                addf2(a0, a1);
                float2 lh = unpack2(a0);
                hlg[rr] = lh.x + lh.y;
                lg_sh[buf][p][h][rr][lane] = hlg[rr];
            }
            bar_pair(1 + p);   // only the partner warp needs the exchange
            // --- phase 2: combine halves + 4 interleaved 32-lane softmaxes ---
            float ex[4], ss[4];
#pragma unroll
            for (int rr = 0; rr < 4; rr++) {
                float lgf = hlg[rr] + lg_sh[buf][p][1 - h][rr][lane];
                ex[rr] = __expf(lgf);
                ss[rr] = ex[rr];
            }
#pragma unroll
            for (int off = 16; off; off >>= 1) {
#pragma unroll
                for (int rr = 0; rr < 4; rr++)
                    ss[rr] += __shfl_xor_sync(0xffffffffu, ss[rr], off);
            }
            unsigned long long c2[4];
#pragma unroll
            for (int rr = 0; rr < 4; rr++) {
                float c = __fdividef(ex[rr], ss[rr]);
                c2[rr] = pack2(c, c);
            }
            // --- phase 3: s[n, my-half] += c * u[l, my-half] ---
#pragma unroll
            for (int rr = 0; rr < 4; rr++) {
                unsigned addr = ush_addr +
                    (unsigned)((p * 16 + rb * 4 + rr) * 256 + h * 128);
                unsigned long long ua[8], ub[8];
#pragma unroll
                for (int k = 0; k < 8; k++)          // batch loads: MLP=8
                    lds_v2b64(ua[k], ub[k], addr + k * 16);
#pragma unroll
                for (int k = 0; k < 8; k++) {        // then the accumulate
                    ffma2(sreg[2 * k + 0], c2[rr], ua[k]);
                    ffma2(sreg[2 * k + 1], c2[rr], ub[k]);
                }
            }
        }
    }

    // Cross-pair combine: pair 0 stores, pair 1 accumulates in place.
    __syncthreads();
    unsigned long long* rp = (unsigned long long*)&red[lane * 66 + h * 32];
    if (p == 0) {
#pragma unroll
        for (int k = 0; k < 16; k++) rp[k] = sreg[k];
    }
    __syncthreads();
    if (p == 1) {
#pragma unroll
        for (int k = 0; k < 16; k++) {
            unsigned long long x = rp[k];
            addf2(x, sreg[k]);
            rp[k] = x;
        }
    }
    __syncthreads();
    float* gp = g_part + ((size_t)b * NCH + ch) * (NC * DIN);
    for (int e = t; e < NC * DIN; e += 128)
        gp[e] = red[(e >> 6) * 66 + (e & 63)];
}

// ----------------------------------------------------------------------------
extern "C" void kernel_launch(void* const* d_in, const int* in_sizes, int n_in,
                              void* d_out, int out_size) {
    (void)n_in; (void)out_size;
    const float* u = (const float*)d_in[0];
    const float* W = (const float*)d_in[1];
    if (in_sizes[0] < in_sizes[1]) {  // defensive: u is the big tensor
        const float* tmp = u; u = W; W = tmp;
    }
    float* out = (float*)d_out;

    dim3 g0(NCH0, BB), gi(NCH, BB), gf(NC, BB);

    // iteration 0: uniform c -> plain sum over l            (launch 0)
    reduce0_kernel<<<g0, 256>>>(u);
    finalize_kernel<<<gf, 128>>>(0, W, nullptr, 1);          // launch 1
    // iteration 1
    iter_kernel<<<gi, 128>>>(u);                             // launch 2
    finalize_kernel<<<gf, 128>>>(1, W, nullptr, 1);          // launch 3
    dummy_kernel<<<1, 32>>>();                               // launch 4 (ncu align)
    // iteration 2 (final)
    iter_kernel<<<gi, 128>>>(u);                             // launch 5 <- profiled
    finalize_kernel<<<gf, 128>>>(1, W, out, 0);              // launch 6
}

// round 14
// speedup vs baseline: 1.0582x; 1.0582x over previous
#include <cuda_runtime.h>

#define BB   32
#define LL   2048
#define DIN  64
#define NC   32
#define DC   16
#define NOUT 512        // NC*DC
#define NCH  16         // chunks for heavy iter kernel
#define LCH  (LL/NCH)   // 128 rows per CTA
#define TILES 4         // 32-row tiles
#define NCH0 32         // chunks for iteration-0 reduction
#define ROWS0 (LL/NCH0) // 64 rows per CTA

// Scratch (no allocations allowed) ------------------------------------------
__device__ __align__(16) float g_part0[BB * NCH0 * DIN];      // 256 KB
__device__ __align__(16) float g_part [BB * NCH  * NC * DIN]; // 4 MB
__device__ __align__(16) float g_v    [BB * NC * DIN];

// Packed f32x2 helpers -------------------------------------------------------
__device__ __forceinline__ void ffma2(unsigned long long& d,
                                      unsigned long long a,
                                      unsigned long long b) {
    asm volatile("fma.rn.f32x2 %0, %1, %2, %0;" : "+l"(d) : "l"(a), "l"(b));
}
__device__ __forceinline__ void addf2(unsigned long long& d, unsigned long long a) {
    asm volatile("add.rn.f32x2 %0, %0, %1;" : "+l"(d) : "l"(a));
}
__device__ __forceinline__ void lds_v2b64(unsigned long long& a,
                                          unsigned long long& b,
                                          unsigned addr) {
    asm volatile("ld.shared.v2.b64 {%0, %1}, [%2];" : "=l"(a), "=l"(b) : "r"(addr));
}
__device__ __forceinline__ unsigned long long pack2(float x, float y) {
    unsigned long long r;
    asm("mov.b64 %0, {%1, %2};" : "=l"(r) : "f"(x), "f"(y));
    return r;
}
__device__ __forceinline__ float2 unpack2(unsigned long long v) {
    float2 r;
    asm("mov.b64 {%0, %1}, %2;" : "=f"(r.x), "=f"(r.y) : "l"(v));
    return r;
}
__device__ __forceinline__ void bar_pair(int id) {
    asm volatile("bar.sync %0, 64;" :: "r"(id));
}
__device__ __forceinline__ void cp_async16(unsigned saddr, const void* gaddr) {
    asm volatile("cp.async.ca.shared.global [%0], [%1], 16;"
                 :: "r"(saddr), "l"(gaddr));
}
__device__ __forceinline__ void cp_commit() {
    asm volatile("cp.async.commit_group;");
}
template <int N>
__device__ __forceinline__ void cp_wait() {
    asm volatile("cp.async.wait_group %0;" :: "n"(N));
}
__device__ __forceinline__ float4 f4add(float4 a, float4 b) {
    a.x += b.x; a.y += b.y; a.z += b.z; a.w += b.w; return a;
}

// ----------------------------------------------------------------------------
// Kernel 1: iteration-0 reduction (vectorized). c = softmax(0) is uniform, so
// s is (up to scale; squash is scale-invariant) just sum_l u[b,l,i].
// grid (NCH0, B), block 256. Each CTA reduces 64 rows of 64 floats.
// Thread t: row-group r0 = t/16, dim-quad d4 = t%16; sums rows r0+16j.
// ----------------------------------------------------------------------------
__global__ __launch_bounds__(256) void reduce0_kernel(const float* __restrict__ u) {
    int b = blockIdx.y, ch = blockIdx.x;
    int t = threadIdx.x;
    int d4 = t & 15, r0 = t >> 4;

    const float4* ug4 =
        (const float4*)(u + ((size_t)b * LL + (size_t)ch * ROWS0) * DIN);
    float4 acc = ug4[(r0) * 16 + d4];
#pragma unroll
    for (int j = 1; j < 4; j++)
        acc = f4add(acc, ug4[(r0 + 16 * j) * 16 + d4]);

    __shared__ float partf[16][64];
    partf[r0][d4 * 4 + 0] = acc.x;
    partf[r0][d4 * 4 + 1] = acc.y;
    partf[r0][d4 * 4 + 2] = acc.z;
    partf[r0][d4 * 4 + 3] = acc.w;
    __syncthreads();

    if (t < 64) {
        float s = 0.f;
#pragma unroll
        for (int r = 0; r < 16; r++) s += partf[r][t];
        g_part0[((size_t)b * NCH0 + ch) * DIN + t] = s;
    }
}

// ----------------------------------------------------------------------------
// Kernel 2: finalize, one CTA (4 warps) per (b, n) capsule.
// grid (NC, B), block 128. float4 chunk reduction by all 128 threads, then
// warp 0 projects through W_n, squashes, writes out / v.
// ----------------------------------------------------------------------------
__global__ __launch_bounds__(128) void finalize_kernel(int per_n,
                                                       const float* __restrict__ W,
                                                       float* __restrict__ out,
                                                       int want_v) {
    int b = blockIdx.y, n = blockIdx.x;
    int t = threadIdx.x;
    int w = t >> 5, lane = t & 31;
    int f4 = t & 15, chg = t >> 4;   // dim-quad, chunk-group (8 groups)

    // 1. vectorized chunk reduction: 128 threads cover 8 chunk-groups x 16 f4
    float4 acc;
    if (per_n) {
        const float4* gp4 = (const float4*)g_part + (size_t)b * NCH * NC * 16;
        // chunk ch contributes at ((ch*NC + n)*16 + f4); groups of 2 chunks
        acc =        gp4[((size_t)chg * NC + n) * 16 + f4];
        acc = f4add(acc, gp4[((size_t)(chg + 8) * NC + n) * 16 + f4]);
    } else {
        const float4* gp4 = (const float4*)g_part0 + (size_t)b * NCH0 * 16;
        acc =        gp4[(size_t)(chg * 4 + 0) * 16 + f4];
#pragma unroll
        for (int j = 1; j < 4; j++)
            acc = f4add(acc, gp4[(size_t)(chg * 4 + j) * 16 + f4]);
    }

    __shared__ __align__(16) float4 part4[8][16];
    part4[chg][f4] = acc;
    __syncthreads();

    if (w != 0) return;

    __shared__ __align__(16) float s_sh[DIN];
    if (lane < 16) {
        float4 s = part4[0][lane];
#pragma unroll
        for (int g = 1; g < 8; g++) s = f4add(s, part4[g][lane]);
        ((float4*)s_sh)[lane] = s;
    }
    __syncwarp();

    // 2. projection: o[d] = sum_i s[i] * W[i*512 + n*16 + d]
    int d = lane & 15, half = lane >> 4;
    float acc2 = 0.f;
    {
        const float* Wp = W + (size_t)(half * 32) * NOUT + n * DC + d;
#pragma unroll
        for (int i = 0; i < 32; i++)
            acc2 += s_sh[half * 32 + i] * Wp[(size_t)i * NOUT];
    }
    acc2 += __shfl_xor_sync(0xffffffffu, acc2, 16);

    // 3. squash (pure L2 normalize, eps=1e-7), reduce within 16-lane group
    float s2 = acc2 * acc2;
#pragma unroll
    for (int off = 8; off; off >>= 1)
        s2 += __shfl_xor_sync(0xffffffffu, s2, off, 16);
    float o = acc2 * rsqrtf(s2 + 1e-7f);

    if (out && lane < 16) out[(size_t)b * NOUT + n * DC + lane] = o;

    // 4. v[i] = sum_d o[d] * W[i*512 + n*16 + d]
    if (want_v) {
        const float4* w0 = (const float4*)(W + (size_t)lane * NOUT + n * DC);
        const float4* w1 = (const float4*)(W + (size_t)(lane + 32) * NOUT + n * DC);
        float v0 = 0.f, v1 = 0.f;
#pragma unroll
        for (int q = 0; q < 4; q++) {
            float4 a = w0[(size_t)q];
            float4 c = w1[(size_t)q];
            float o0 = __shfl_sync(0xffffffffu, o, 4 * q + 0);
            float o1 = __shfl_sync(0xffffffffu, o, 4 * q + 1);
            float o2 = __shfl_sync(0xffffffffu, o, 4 * q + 2);
            float o3 = __shfl_sync(0xffffffffu, o, 4 * q + 3);
            v0 += a.x * o0 + a.y * o1 + a.z * o2 + a.w * o3;
            v1 += c.x * o0 + c.y * o1 + c.z * o2 + c.w * o3;
        }
        float* vp = g_v + ((size_t)b * NC + n) * DIN;
        vp[lane] = v0;
        vp[lane + 32] = v1;
    }
}

// ----------------------------------------------------------------------------
// Kernel 3: fused routing iteration, i-split across warp pairs (proven R8
// version, unchanged — measured at ~75-80%% of the fp32-FMA roofline).
// grid (NCH, B), block 128 (4 warps = 2 pairs; pair handles 16 rows/tile).
// ----------------------------------------------------------------------------
__global__ __launch_bounds__(128, 4) void iter_kernel(const float* __restrict__ u) {
    int b = blockIdx.y, ch = blockIdx.x;
    int t = threadIdx.x, w = t >> 5, lane = t & 31;
    int p = w >> 1, h = w & 1;

    __shared__ __align__(16) float4 ush4[2][32 * 16];       // 2 x 8 KB tiles
    __shared__ __align__(16) float  lg_sh[2][2][2][4][32];  // logits exch (4 KB)
    __shared__ __align__(16) float  red[32 * 66];           // s combine (8.25 KB)

    unsigned long long vreg[16], sreg[16];
    const unsigned long long* vp =
        (const unsigned long long*)(g_v + ((size_t)b * NC + lane) * DIN + h * 32);
#pragma unroll
    for (int k = 0; k < 16; k++) vreg[k] = vp[k];
#pragma unroll
    for (int k = 0; k < 16; k++) sreg[k] = 0ULL;

    unsigned ush_base = (unsigned)__cvta_generic_to_shared(&ush4[0][0]);
    const float4* ug = (const float4*)(u + ((size_t)b * LL + (size_t)ch * LCH) * DIN);

    // prologue: async-load tile 0 into buffer 0
#pragma unroll
    for (int j = 0; j < 4; j++)
        cp_async16(ush_base + (unsigned)((t + 128 * j) * 16), ug + t + 128 * j);
    cp_commit();

    for (int tile = 0; tile < TILES; tile++) {
        cp_wait<0>();        // tile's data resident
        __syncthreads();     // all warps done with the buffer we're about to fill

        if (tile + 1 < TILES) {
            unsigned dst = ush_base + (unsigned)(((tile + 1) & 1) * 8192);
            const float4* src = ug + (tile + 1) * 512;
#pragma unroll
            for (int j = 0; j < 4; j++)
                cp_async16(dst + (unsigned)((t + 128 * j) * 16), src + t + 128 * j);
            cp_commit();
        }

        unsigned ush_addr = ush_base + (unsigned)((tile & 1) * 8192);

        for (int rb = 0; rb < 4; rb++) {     // 4 batches of 4 rows per pair
            int buf = rb & 1;
            float hlg[4];
            // --- phase 1: half-logits for 4 rows (my 32 dims) ---
#pragma unroll
            for (int rr = 0; rr < 4; rr++) {
                unsigned addr = ush_addr +
                    (unsigned)((p * 16 + rb * 4 + rr) * 256 + h * 128);
                unsigned long long ua[8], ub[8];
#pragma unroll
                for (int k = 0; k < 8; k++)          // batch loads: MLP=8
                    lds_v2b64(ua[k], ub[k], addr + k * 16);
                unsigned long long a0 = 0ULL, a1 = 0ULL;
#pragma unroll
                for (int k = 0; k < 8; k++) {        // then the math
                    ffma2(a0, ua[k], vreg[2 * k + 0]);
                    ffma2(a1, ub[k], vreg[2 * k + 1]);
                }
                addf2(a0, a1);
                float2 lh = unpack2(a0);
                hlg[rr] = lh.x + lh.y;
                lg_sh[buf][p][h][rr][lane] = hlg[rr];
            }
            bar_pair(1 + p);   // only the partner warp needs the exchange
            // --- phase 2: combine halves + 4 interleaved 32-lane softmaxes ---
            float ex[4], ss[4];
#pragma unroll
            for (int rr = 0; rr < 4; rr++) {
                float lgf = hlg[rr] + lg_sh[buf][p][1 - h][rr][lane];
                ex[rr] = __expf(lgf);
                ss[rr] = ex[rr];
            }
#pragma unroll
            for (int off = 16; off; off >>= 1) {
#pragma unroll
                for (int rr = 0; rr < 4; rr++)
                    ss[rr] += __shfl_xor_sync(0xffffffffu, ss[rr], off);
            }
            unsigned long long c2[4];
#pragma unroll
            for (int rr = 0; rr < 4; rr++) {
                float c = __fdividef(ex[rr], ss[rr]);
                c2[rr] = pack2(c, c);
            }
            // --- phase 3: s[n, my-half] += c * u[l, my-half] ---
#pragma unroll
            for (int rr = 0; rr < 4; rr++) {
                unsigned addr = ush_addr +
                    (unsigned)((p * 16 + rb * 4 + rr) * 256 + h * 128);
                unsigned long long ua[8], ub[8];
#pragma unroll
                for (int k = 0; k < 8; k++)          // batch loads: MLP=8
                    lds_v2b64(ua[k], ub[k], addr + k * 16);
#pragma unroll
                for (int k = 0; k < 8; k++) {        // then the accumulate
                    ffma2(sreg[2 * k + 0], c2[rr], ua[k]);
                    ffma2(sreg[2 * k + 1], c2[rr], ub[k]);
                }
            }
        }
    }

    // Cross-pair combine: pair 0 stores, pair 1 accumulates in place.
    __syncthreads();
    unsigned long long* rp = (unsigned long long*)&red[lane * 66 + h * 32];
    if (p == 0) {
#pragma unroll
        for (int k = 0; k < 16; k++) rp[k] = sreg[k];
    }
    __syncthreads();
    if (p == 1) {
#pragma unroll
        for (int k = 0; k < 16; k++) {
            unsigned long long x = rp[k];
            addf2(x, sreg[k]);
            rp[k] = x;
        }
    }
    __syncthreads();
    float* gp = g_part + ((size_t)b * NCH + ch) * (NC * DIN);
    for (int e = t; e < NC * DIN; e += 128)
        gp[e] = red[(e >> 6) * 66 + (e & 63)];
}

// ----------------------------------------------------------------------------
extern "C" void kernel_launch(void* const* d_in, const int* in_sizes, int n_in,
                              void* d_out, int out_size) {
    (void)n_in; (void)out_size;
    const float* u = (const float*)d_in[0];
    const float* W = (const float*)d_in[1];
    if (in_sizes[0] < in_sizes[1]) {  // defensive: u is the big tensor
        const float* tmp = u; u = W; W = tmp;
    }
    float* out = (float*)d_out;

    dim3 g0(NCH0, BB), gi(NCH, BB), gf(NC, BB);

    // iteration 0: uniform c -> plain sum over l
    reduce0_kernel<<<g0, 256>>>(u);
    finalize_kernel<<<gf, 128>>>(0, W, nullptr, 1);
    // iteration 1
    iter_kernel<<<gi, 128>>>(u);
    finalize_kernel<<<gf, 128>>>(1, W, nullptr, 1);
    // iteration 2 (final)
    iter_kernel<<<gi, 128>>>(u);
    finalize_kernel<<<gf, 128>>>(1, W, out, 0);
}